// round 14
// baseline (speedup 1.0000x reference)
#include <cuda_runtime.h>
#include <math.h>

// Problem constants (fixed shapes for HoughSplitLoss_12884901888574)
#define B_   32
#define L_   6
#define A_   1024
#define R_   1024
#define NPTS (B_ * L_)            // 192
#define RAD  5
#define WIN  11                   // 2*RAD+1
#define NWIN (WIN * WIN)          // 121
#define NELEM (1024u * 1024u)     // per-batch plane elements
#define TOTAL_ELEMS ((long long)B_ * A_ * R_)  // 33554432

#define NTHR   512                // 16 warps/block, one point per warp (optimum)
#define WARPS  (NTHR / 32)        // 16
#define NBLK   (NPTS / WARPS)     // 12 blocks

// Fixed-point scale: per-lane int32 quantization, summed with hardware REDUX
// (order-independent -> deterministic). Per-lane value <= ~1.6*2^22 < 2^23;
// warp sum < 2^31; block sum < 2^35; total < 2^39.
#define SCALE_MAIN 4194304.0f     // 2^22

// Block-local arrival tag (shared-memory accumulator): low 48 bits sum,
// bits 48+ arrival count. Global tag at bit 58.
#define STAG       (1ULL << 48)
#define SSUM_MASK  (STAG - 1ULL)
#define ARRIVE_TAG (1ULL << 58)
#define SUM_MASK   (ARRIVE_TAG - 1ULL)

// Zero at module load; the elected deciding warp resets it after reading, so
// every launch / graph replay sees identical initial state -> deterministic.
__device__ unsigned long long g_acc;

__device__ __forceinline__ float sigmoidf_(float x) {
    return __frcp_rn(1.0f + __expf(-x));
}

// Gather one 11x11 window (lane covers cells lane+32*it, MLP=8) and return
// the lane-partial sum of |sigmoid(pre)-gt| over in-bounds cells.
__device__ __forceinline__ float gather_window(
    const float* __restrict__ pre_hough,
    const float* __restrict__ gt_hough,
    int b, int X, int Y, int lane)
{
    float vp[4], vg[4];
    bool  ok[4];
    #pragma unroll
    for (int it = 0; it < 4; ++it) {
        const int idx = lane + it * 32;
        const int di  = idx / WIN - RAD;      // lane-only math: ready early
        const int dj  = idx % WIN - RAD;
        const int xi  = X + di;
        const int yi  = Y + dj;
        ok[it] = (idx < NWIN) & (xi >= 0) & (xi < R_) & (yi >= 0) & (yi < A_);
        const size_t off = (size_t)b * NELEM
                         + (size_t)(ok[it] ? xi : 0) * R_ + (ok[it] ? yi : 0);
        vp[it] = pre_hough[off];
        vg[it] = gt_hough[off];
    }
    float acc = 0.0f;
    #pragma unroll
    for (int it = 0; it < 4; ++it)
        if (ok[it]) acc += fabsf(sigmoidf_(vp[it]) - vg[it]);
    return acc;
}

// ---------------------------------------------------------------------------
// 12 blocks x 512 threads; warp = point.
// Schedule: issue ALL point loads (g, pre-points, gt-points) FIRST, then the
// s_acc-init __syncthreads (BAR does not drain LDGs -> their latency hides
// under the barrier), then gather as soon as g lands. Tail is barrier-free:
// warp REDUX -> lane0 tagged ATOMS into s_acc; last-arriving warp's return
// value IS the block sum -> it alone issues the tagged global atomic; the
// chip-wide last block decides and writes out.
// ---------------------------------------------------------------------------
__global__ __launch_bounds__(NTHR)
void loss_fused(const float* __restrict__ pre_hough,
                const float* __restrict__ gt_hough,
                const int*   __restrict__ in_pre_points,
                const int*   __restrict__ gt_points,
                float*       __restrict__ out)
{
    __shared__ unsigned long long s_acc;

    const int tid  = threadIdx.x;
    const int warp = tid >> 5;
    const int lane = tid & 31;
    const int p    = blockIdx.x * WARPS + warp;   // 0..191
    const int b    = p / L_;
    const int l    = p - b * L_;

    if (tid == 0) s_acc = 0ULL;

    // ---- Issue ALL point loads BEFORE the barrier (latency hides under it) ----
    const int2  g   = ((const int2*)(gt_points + b * (L_ * 2)))[l];
    const int4* pp  = (const int4*)(in_pre_points + b * (L_ * 2));
    const int4* ggv = (const int4*)(gt_points     + b * (L_ * 2));
    const int4 v0 = pp[0],  v1 = pp[1],  v2 = pp[2];
    const int4 w0 = ggv[0], w1 = ggv[1], w2 = ggv[2];

    __syncthreads();               // orders s_acc init only; LDGs stay in flight

    // ---- Speculative gather from gt coordinates (bounds-masked => safe) ----
    float acc = gather_window(pre_hough, gt_hough, b, g.x, g.y, lane);
    float W   = 1.0f / (float)(RAD * RAD);   // fast-path weight

    const int minpx = min(min(min(v0.x, v0.z), min(v1.x, v1.z)), min(v2.x, v2.z));
    const int mingx = min(min(min(w0.x, w0.z), min(w1.x, w1.z)), min(w2.x, w2.z));

    // ---- Rare path: some invalid point in this batch -> full reference
    //      semantics (stable sort, pre-point fallback, weights), re-gather ----
    if ((minpx < 0) | (mingx < 0)) {
        int px[L_] = { v0.x, v0.z, v1.x, v1.z, v2.x, v2.z };
        int py[L_] = { v0.y, v0.w, v1.y, v1.w, v2.y, v2.w };
        // 32-bit keys: valid key <= 999*10000+999 < 2^30 = BIG_KEY.
        int key[L_];
        #pragma unroll
        for (int i = 0; i < L_; ++i)
            key[i] = (px[i] < 0) ? (1 << 30) : px[i] * 10000 + py[i];
        // Stable insertion sort (matches stable argsort).
        #pragma unroll
        for (int i = 1; i < L_; ++i) {
            int kk = key[i], kx = px[i], ky = py[i];
            int j = i - 1;
            while (j >= 0 && key[j] > kk) {
                key[j + 1] = key[j]; px[j + 1] = px[j]; py[j + 1] = py[j];
                --j;
            }
            key[j + 1] = kk; px[j + 1] = kx; py[j + 1] = ky;
        }
        const bool use_gt   = (g.x >= 0);
        const bool one_inv  = (px[l] < 0) || (g.x < 0);
        const bool both_inv = (px[l] < 0) && (g.x < 0);
        const int X = use_gt ? g.x : px[l];
        const int Y = use_gt ? g.y : py[l];
        W   = both_inv ? 0.0f : (one_inv ? 10.0f : 1.0f) / (float)(RAD * RAD);
        acc = gather_window(pre_hough, gt_hough, b, X, Y, lane);
    }

    // ---- Per-lane quantize (order-independent from here), hardware REDUX ----
    const unsigned qlane = (unsigned)__float2int_rn(acc * W * SCALE_MAIN);
    const unsigned qwarp = __reduce_add_sync(0xffffffffu, qlane);

    // ---- Barrier-free block merge: tagged ATOMS; last warp carries on ----
    unsigned fb = 0;
    if (lane == 0) {
        const unsigned long long smine = (unsigned long long)qwarp + STAG;
        const unsigned long long sold  = atomicAdd(&s_acc, smine);
        if ((sold >> 48) == (unsigned long long)(WARPS - 1)) {
            const unsigned long long blocksum = (sold + smine) & SSUM_MASK;
            const unsigned long long mine = blocksum + ARRIVE_TAG;
            const unsigned long long old  = atomicAdd(&g_acc, mine);
            if ((old >> 58) == (unsigned long long)(NBLK - 1)) {
                const unsigned long long total_q = (old + mine) & SUM_MASK;
                g_acc = 0ULL;       // restore invariant for next replay
                const float total = (float)((double)total_q / (double)SCALE_MAIN);
                if (total != 0.0f) {
                    out[0] = total / (float)B_;
                } else {
                    fb = 1u;        // this warp alone runs the fallback
                }
            }
        }
    }
    fb = __shfl_sync(0xffffffffu, fb, 0);

    // ---- Fallback: ONE warp, only when total == 0 (never on this data;
    //      correctness-only path, speed irrelevant) ----
    if (fb) {
        double d = 0.0;
        for (long long i = lane; i < TOTAL_ELEMS; i += 32)
            d += (double)fabsf(1.0f / (1.0f + expf(-pre_hough[i])) - gt_hough[i]);
        // Deterministic warp tree-reduce in double via shuffles.
        #pragma unroll
        for (int off = 16; off > 0; off >>= 1)
            d += __shfl_down_sync(0xffffffffu, d, off);
        if (lane == 0)
            out[0] = (float)(d / (double)TOTAL_ELEMS);
    }
}

// ---------------------------------------------------------------------------
extern "C" void kernel_launch(void* const* d_in, const int* in_sizes, int n_in,
                              void* d_out, int out_size)
{
    const float* pre_hough     = (const float*)d_in[0];
    const float* gt_hough      = (const float*)d_in[1];
    const int*   in_pre_points = (const int*)d_in[2];
    const int*   gt_points     = (const int*)d_in[3];
    float*       out           = (float*)d_out;

    loss_fused<<<NBLK, NTHR>>>(pre_hough, gt_hough, in_pre_points, gt_points, out);
}

// round 15
// speedup vs baseline: 1.0048x; 1.0048x over previous
#include <cuda_runtime.h>
#include <math.h>

// Problem constants (fixed shapes for HoughSplitLoss_12884901888574)
#define B_   32
#define L_   6
#define A_   1024
#define R_   1024
#define NPTS (B_ * L_)            // 192
#define RAD  5
#define WIN  11                   // 2*RAD+1
#define NWIN (WIN * WIN)          // 121
#define NELEM (1024u * 1024u)     // per-batch plane elements
#define TOTAL_ELEMS ((long long)B_ * A_ * R_)  // 33554432

#define NTHR   512                // 16 warps/block, one point per warp
#define WARPS  (NTHR / 32)        // 16
#define NBLK   (NPTS / WARPS)     // 12 blocks (measured optimum: 24 and 6 both slower)

// Fixed-point scale: per-lane int32 quantization, summed with hardware REDUX
// (order-independent -> deterministic). Per-lane value <= ~1.6*2^22 < 2^23;
// warp sum < 2^31; block sum < 2^35; total < 2^39.
#define SCALE_MAIN 4194304.0f     // 2^22

// Arrival tag packed into the accumulator's high bits: one atomicAdd is both
// merge and arrival counter. Low 58 bits: non-negative fixed-point sum.
#define ARRIVE_TAG (1ULL << 58)
#define SUM_MASK   (ARRIVE_TAG - 1ULL)

// Zero at module load; elected last block resets it after reading, so every
// launch / graph replay sees identical initial state -> deterministic.
__device__ unsigned long long g_acc;

__device__ __forceinline__ float sigmoidf_(float x) {
    return __frcp_rn(1.0f + __expf(-x));
}

// Gather one 11x11 window (lane covers cells lane+32*it, MLP=8) and return
// the lane-partial sum of |sigmoid(pre)-gt| over in-bounds cells.
__device__ __forceinline__ float gather_window(
    const float* __restrict__ pre_hough,
    const float* __restrict__ gt_hough,
    int b, int X, int Y, int lane)
{
    float vp[4], vg[4];
    bool  ok[4];
    #pragma unroll
    for (int it = 0; it < 4; ++it) {
        const int idx = lane + it * 32;
        const int di  = idx / WIN - RAD;      // lane-only math: ready early
        const int dj  = idx % WIN - RAD;
        const int xi  = X + di;
        const int yi  = Y + dj;
        ok[it] = (idx < NWIN) & (xi >= 0) & (xi < R_) & (yi >= 0) & (yi < A_);
        const size_t off = (size_t)b * NELEM
                         + (size_t)(ok[it] ? xi : 0) * R_ + (ok[it] ? yi : 0);
        vp[it] = pre_hough[off];
        vg[it] = gt_hough[off];
    }
    float acc = 0.0f;
    #pragma unroll
    for (int it = 0; it < 4; ++it)
        if (ok[it]) acc += fabsf(sigmoidf_(vp[it]) - vg[it]);
    return acc;
}

// ---------------------------------------------------------------------------
// 12 blocks x 512 threads; warp = point.
// Critical path: LDG gt(int2) -> gather LDGs -> per-lane quantize -> REDUX
// -> smem -> warp0 parallel funnel (REDUX) -> ONE tagged global atomic.
// Pre-point loads overlap the gather and feed only the rare path.
// ---------------------------------------------------------------------------
__global__ __launch_bounds__(NTHR)
void loss_fused(const float* __restrict__ pre_hough,
                const float* __restrict__ gt_hough,
                const int*   __restrict__ in_pre_points,
                const int*   __restrict__ gt_points,
                float*       __restrict__ out)
{
    __shared__ unsigned s_q[WARPS];
    __shared__ int      s_fb;       // 1 => this block runs the fallback
    __shared__ double   s_red[256];

    const int tid  = threadIdx.x;
    const int warp = tid >> 5;
    const int lane = tid & 31;
    const int p    = blockIdx.x * WARPS + warp;   // 0..191
    const int b    = p / L_;
    const int l    = p - b * L_;

    if (tid == 0) s_fb = 0;

    // ---- Chain head: ONE int2 load decides the (common-path) addresses ----
    const int2 g = ((const int2*)(gt_points + b * (L_ * 2)))[l];

    // ---- Speculative gather from gt coordinates (bounds-masked => safe) ----
    float acc = gather_window(pre_hough, gt_hough, b, g.x, g.y, lane);
    float W   = 1.0f / (float)(RAD * RAD);   // fast-path weight

    // ---- Overlapped: pre/gt point loads for the validity check ----
    const int4* pp  = (const int4*)(in_pre_points + b * (L_ * 2));
    const int4* ggv = (const int4*)(gt_points     + b * (L_ * 2));
    const int4 v0 = pp[0],  v1 = pp[1],  v2 = pp[2];
    const int4 w0 = ggv[0], w1 = ggv[1], w2 = ggv[2];
    const int minpx = min(min(min(v0.x, v0.z), min(v1.x, v1.z)), min(v2.x, v2.z));
    const int mingx = min(min(min(w0.x, w0.z), min(w1.x, w1.z)), min(w2.x, w2.z));

    // ---- Rare path: some invalid point in this batch -> full reference
    //      semantics (stable sort, pre-point fallback, weights), re-gather ----
    if ((minpx < 0) | (mingx < 0)) {
        int px[L_] = { v0.x, v0.z, v1.x, v1.z, v2.x, v2.z };
        int py[L_] = { v0.y, v0.w, v1.y, v1.w, v2.y, v2.w };
        // 32-bit keys: valid key <= 999*10000+999 < 2^30 = BIG_KEY.
        int key[L_];
        #pragma unroll
        for (int i = 0; i < L_; ++i)
            key[i] = (px[i] < 0) ? (1 << 30) : px[i] * 10000 + py[i];
        // Stable insertion sort (matches stable argsort).
        #pragma unroll
        for (int i = 1; i < L_; ++i) {
            int kk = key[i], kx = px[i], ky = py[i];
            int j = i - 1;
            while (j >= 0 && key[j] > kk) {
                key[j + 1] = key[j]; px[j + 1] = px[j]; py[j + 1] = py[j];
                --j;
            }
            key[j + 1] = kk; px[j + 1] = kx; py[j + 1] = ky;
        }
        const bool use_gt   = (g.x >= 0);
        const bool one_inv  = (px[l] < 0) || (g.x < 0);
        const bool both_inv = (px[l] < 0) && (g.x < 0);
        const int X = use_gt ? g.x : px[l];
        const int Y = use_gt ? g.y : py[l];
        W   = both_inv ? 0.0f : (one_inv ? 10.0f : 1.0f) / (float)(RAD * RAD);
        acc = gather_window(pre_hough, gt_hough, b, X, Y, lane);
    }

    // ---- Per-lane quantize (order-independent from here), hardware REDUX ----
    const unsigned qlane = (unsigned)__float2int_rn(acc * W * SCALE_MAIN);
    const unsigned qwarp = __reduce_add_sync(0xffffffffu, qlane);
    if (lane == 0) s_q[warp] = qwarp;
    __syncthreads();

    // ---- Parallel block funnel (warp 0) + single tagged atomic ----
    if (warp == 0) {
        const unsigned mypart = (lane < WARPS) ? s_q[lane] : 0u;
        const unsigned qs     = __reduce_add_sync(0xffffffffu, mypart);
        if (lane == 0) {
            const unsigned long long mine = (unsigned long long)qs + ARRIVE_TAG;
            const unsigned long long old  = atomicAdd(&g_acc, mine);
            if ((old >> 58) == (unsigned long long)(NBLK - 1)) {
                const unsigned long long total_q = (old + mine) & SUM_MASK;
                g_acc = 0ULL;           // restore invariant for next replay
                const float total = (float)((double)total_q / (double)SCALE_MAIN);
                if (total != 0.0f) {
                    out[0] = total / (float)B_;
                } else {
                    s_fb = 1;           // this block alone runs the fallback
                }
            }
        }
    }
    __syncthreads();

    // ---- Fallback: ONE block, only when total == 0 (never on this data) ----
    if (s_fb) {
        if (tid < 256) {
            double d = 0.0;
            for (long long i = tid; i < TOTAL_ELEMS; i += 256)
                d += (double)fabsf(1.0f / (1.0f + expf(-pre_hough[i])) - gt_hough[i]);
            s_red[tid] = d;
        }
        __syncthreads();
        for (int off = 128; off > 0; off >>= 1) {
            if (tid < off) s_red[tid] += s_red[tid + off];
            __syncthreads();
        }
        if (tid == 0)
            out[0] = (float)(s_red[0] / (double)TOTAL_ELEMS);
    }
}

// ---------------------------------------------------------------------------
extern "C" void kernel_launch(void* const* d_in, const int* in_sizes, int n_in,
                              void* d_out, int out_size)
{
    const float* pre_hough     = (const float*)d_in[0];
    const float* gt_hough      = (const float*)d_in[1];
    const int*   in_pre_points = (const int*)d_in[2];
    const int*   gt_points     = (const int*)d_in[3];
    float*       out           = (float*)d_out;

    loss_fused<<<NBLK, NTHR>>>(pre_hough, gt_hough, in_pre_points, gt_points, out);
}

// round 16
// speedup vs baseline: 1.0097x; 1.0048x over previous
#include <cuda_runtime.h>
#include <math.h>

// Problem constants (fixed shapes for HoughSplitLoss_12884901888574)
#define B_   32
#define L_   6
#define A_   1024
#define R_   1024
#define NPTS (B_ * L_)            // 192
#define RAD  5
#define WIN  11                   // 2*RAD+1
#define NWIN (WIN * WIN)          // 121
#define NELEM (1024u * 1024u)     // per-batch plane elements
#define TOTAL_ELEMS ((long long)B_ * A_ * R_)  // 33554432

#define NTHR   512                // 16 warps/block, one point per warp
#define WARPS  (NTHR / 32)        // 16
#define NBLK   (NPTS / WARPS)     // 12 blocks (measured optimum)

// Fixed-point scale: per-lane int32 quantization, summed with hardware REDUX
// (order-independent -> deterministic). Per-warp value < 2^31; total over all
// 192 warps < 2^33 -> fits the low-40-bit sum field.
#define SCALE_MAIN 4194304.0f     // 2^22

// Arrival tag at bit 40: one atomicAdd per WARP is both merge and arrival
// counter (192 arrivals << 2^24 headroom). Same-address u64 atomics pipeline
// at ~REDG rate under contention, so 192 ops cost ~160 cy at L2 total.
#define ARRIVE_TAG (1ULL << 40)
#define SUM_MASK   (ARRIVE_TAG - 1ULL)

// Zero at module load; the deciding warp resets it after reading, so every
// launch / graph replay sees identical initial state -> deterministic.
__device__ unsigned long long g_acc;

__device__ __forceinline__ float sigmoidf_(float x) {
    return __frcp_rn(1.0f + __expf(-x));
}

// Gather one 11x11 window (lane covers cells lane+32*it, MLP=8) and return
// the lane-partial sum of |sigmoid(pre)-gt| over in-bounds cells.
__device__ __forceinline__ float gather_window(
    const float* __restrict__ pre_hough,
    const float* __restrict__ gt_hough,
    int b, int X, int Y, int lane)
{
    float vp[4], vg[4];
    bool  ok[4];
    #pragma unroll
    for (int it = 0; it < 4; ++it) {
        const int idx = lane + it * 32;
        const int di  = idx / WIN - RAD;      // lane-only math: ready early
        const int dj  = idx % WIN - RAD;
        const int xi  = X + di;
        const int yi  = Y + dj;
        ok[it] = (idx < NWIN) & (xi >= 0) & (xi < R_) & (yi >= 0) & (yi < A_);
        const size_t off = (size_t)b * NELEM
                         + (size_t)(ok[it] ? xi : 0) * R_ + (ok[it] ? yi : 0);
        vp[it] = pre_hough[off];
        vg[it] = gt_hough[off];
    }
    float acc = 0.0f;
    #pragma unroll
    for (int it = 0; it < 4; ++it)
        if (ok[it]) acc += fabsf(sigmoidf_(vp[it]) - vg[it]);
    return acc;
}

// ---------------------------------------------------------------------------
// 12 blocks x 512 threads; warp = point. ZERO intra-block coordination:
// no __syncthreads, no shared memory. Each warp: gt load -> speculative
// gather -> per-lane quantize -> warp REDUX -> lane0 tagged global atomic.
// The warp whose atomic return shows 191 prior arrivals is the decider: its
// (old + mine) low bits ARE the final total; it writes out and resets g_acc.
// Same-address u64 atomics pipeline at L2 (~REDG rate), so the 192-op funnel
// is ~160 cy total, off everyone's critical path except the decider's.
// ---------------------------------------------------------------------------
__global__ __launch_bounds__(NTHR)
void loss_fused(const float* __restrict__ pre_hough,
                const float* __restrict__ gt_hough,
                const int*   __restrict__ in_pre_points,
                const int*   __restrict__ gt_points,
                float*       __restrict__ out)
{
    const int tid  = threadIdx.x;
    const int warp = tid >> 5;
    const int lane = tid & 31;
    const int p    = blockIdx.x * WARPS + warp;   // 0..191
    const int b    = p / L_;
    const int l    = p - b * L_;

    // ---- Chain head: ONE int2 load decides the (common-path) addresses ----
    const int2 g = ((const int2*)(gt_points + b * (L_ * 2)))[l];

    // ---- Speculative gather from gt coordinates (bounds-masked => safe) ----
    float acc = gather_window(pre_hough, gt_hough, b, g.x, g.y, lane);
    float W   = 1.0f / (float)(RAD * RAD);   // fast-path weight

    // ---- Overlapped: pre/gt point loads for the validity check ----
    const int4* pp  = (const int4*)(in_pre_points + b * (L_ * 2));
    const int4* ggv = (const int4*)(gt_points     + b * (L_ * 2));
    const int4 v0 = pp[0],  v1 = pp[1],  v2 = pp[2];
    const int4 w0 = ggv[0], w1 = ggv[1], w2 = ggv[2];
    const int minpx = min(min(min(v0.x, v0.z), min(v1.x, v1.z)), min(v2.x, v2.z));
    const int mingx = min(min(min(w0.x, w0.z), min(w1.x, w1.z)), min(w2.x, w2.z));

    // ---- Rare path: some invalid point in this batch -> full reference
    //      semantics (stable sort, pre-point fallback, weights), re-gather ----
    if ((minpx < 0) | (mingx < 0)) {
        int px[L_] = { v0.x, v0.z, v1.x, v1.z, v2.x, v2.z };
        int py[L_] = { v0.y, v0.w, v1.y, v1.w, v2.y, v2.w };
        // 32-bit keys: valid key <= 999*10000+999 < 2^30 = BIG_KEY.
        int key[L_];
        #pragma unroll
        for (int i = 0; i < L_; ++i)
            key[i] = (px[i] < 0) ? (1 << 30) : px[i] * 10000 + py[i];
        // Stable insertion sort (matches stable argsort).
        #pragma unroll
        for (int i = 1; i < L_; ++i) {
            int kk = key[i], kx = px[i], ky = py[i];
            int j = i - 1;
            while (j >= 0 && key[j] > kk) {
                key[j + 1] = key[j]; px[j + 1] = px[j]; py[j + 1] = py[j];
                --j;
            }
            key[j + 1] = kk; px[j + 1] = kx; py[j + 1] = ky;
        }
        const bool use_gt   = (g.x >= 0);
        const bool one_inv  = (px[l] < 0) || (g.x < 0);
        const bool both_inv = (px[l] < 0) && (g.x < 0);
        const int X = use_gt ? g.x : px[l];
        const int Y = use_gt ? g.y : py[l];
        W   = both_inv ? 0.0f : (one_inv ? 10.0f : 1.0f) / (float)(RAD * RAD);
        acc = gather_window(pre_hough, gt_hough, b, X, Y, lane);
    }

    // ---- Per-lane quantize (order-independent from here), hardware REDUX ----
    const unsigned qlane = (unsigned)__float2int_rn(acc * W * SCALE_MAIN);
    const unsigned qwarp = __reduce_add_sync(0xffffffffu, qlane);

    // ---- Per-warp tagged global atomic; the 192nd arrival decides ----
    unsigned fb = 0;
    if (lane == 0) {
        const unsigned long long mine = (unsigned long long)qwarp + ARRIVE_TAG;
        const unsigned long long old  = atomicAdd(&g_acc, mine);
        if ((old >> 40) == (unsigned long long)(NPTS - 1)) {
            const unsigned long long total_q = (old + mine) & SUM_MASK;
            g_acc = 0ULL;           // restore invariant for next replay
            const float total = (float)((double)total_q / (double)SCALE_MAIN);
            if (total != 0.0f) {
                out[0] = total / (float)B_;
            } else {
                fb = 1u;            // this warp alone runs the fallback
            }
        }
    }
    fb = __shfl_sync(0xffffffffu, fb, 0);

    // ---- Fallback: ONE warp, only when total == 0 (never on this data;
    //      correctness-only path, speed irrelevant) ----
    if (fb) {
        double d = 0.0;
        for (long long i = lane; i < TOTAL_ELEMS; i += 32)
            d += (double)fabsf(1.0f / (1.0f + expf(-pre_hough[i])) - gt_hough[i]);
        // Deterministic warp tree-reduce in double via shuffles.
        #pragma unroll
        for (int off = 16; off > 0; off >>= 1)
            d += __shfl_down_sync(0xffffffffu, d, off);
        if (lane == 0)
            out[0] = (float)(d / (double)TOTAL_ELEMS);
    }
}

// ---------------------------------------------------------------------------
extern "C" void kernel_launch(void* const* d_in, const int* in_sizes, int n_in,
                              void* d_out, int out_size)
{
    const float* pre_hough     = (const float*)d_in[0];
    const float* gt_hough      = (const float*)d_in[1];
    const int*   in_pre_points = (const int*)d_in[2];
    const int*   gt_points     = (const int*)d_in[3];
    float*       out           = (float*)d_out;

    loss_fused<<<NBLK, NTHR>>>(pre_hough, gt_hough, in_pre_points, gt_points, out);
}